// round 4
// baseline (speedup 1.0000x reference)
#include <cuda_runtime.h>
#include <math.h>

#define NC 128          // hidden / input dim
#define N_MAX 50000
#define E_MAX 800000
#define NG 64

// ---- scratch (static device globals; no allocation allowed) ----
__device__ float g_h[(size_t)N_MAX * NC];
__device__ float g_agg[(size_t)N_MAX * NC];
__device__ float g_asrc[N_MAX];
__device__ float g_adst[N_MAX];
__device__ float g_p[E_MAX];
__device__ float g_denom[N_MAX];
__device__ float g_pool[NG * NC];
__device__ float g_cnt[NG];
__device__ float g_wdst1[NC];
__device__ float g_wdst2[NC];
// normalized int32 graph structure
__device__ int g_src[E_MAX];
__device__ int g_dst[E_MAX];
__device__ int g_batch[N_MAX];
__device__ int g_is64;
// CSR scratch
__device__ int g_deg[N_MAX];
__device__ int g_rowstart[N_MAX];
__device__ int g_cursor[N_MAX];
__device__ int g_csr[E_MAX];

// K-1: detect whether edge_index is int64 or int32.
// If int64 (values < 2^31, nonneg), every odd int32 word is the zero high-half.
__global__ void detect_kernel(const int* __restrict__ ei_words, int E) {
    __shared__ int s_or;
    if (threadIdx.x == 0) s_or = 0;
    __syncthreads();
    int cnt = (E < 2048) ? E : 2048;
    int acc = 0;
    for (int i = threadIdx.x; i < cnt; i += 256) acc |= ei_words[2 * i + 1];
    atomicOr(&s_or, acc);
    __syncthreads();
    if (threadIdx.x == 0) g_is64 = (s_or == 0) ? 1 : 0;
}

// K-0.5: normalize edge_index + batch to int32 scratch.
__global__ void convert_kernel(const void* __restrict__ ei, const void* __restrict__ batch,
                               int E, int n) {
    int i = blockIdx.x * blockDim.x + threadIdx.x;
    int is64 = g_is64;
    if (i < E) {
        if (is64) {
            g_src[i] = (int)((const long long*)ei)[i];
            g_dst[i] = (int)((const long long*)ei)[E + i];
        } else {
            g_src[i] = ((const int*)ei)[i];
            g_dst[i] = ((const int*)ei)[E + i];
        }
    }
    if (i < n) {
        g_batch[i] = is64 ? (int)((const long long*)batch)[i] : ((const int*)batch)[i];
    }
}

// K0: fold W_dst @ att_dst into per-layer 128-vectors; zero pool + deg arrays.
__global__ void prep_kernel(const float* __restrict__ Wd1, const float* __restrict__ ad1,
                            const float* __restrict__ Wd2, const float* __restrict__ ad2,
                            int n) {
    int t = blockIdx.x * blockDim.x + threadIdx.x;
    if (blockIdx.x == 0) {
        int lt = threadIdx.x;  // 256 threads in block 0
        if (lt < NC) {
            float s = 0.f;
            #pragma unroll 4
            for (int c = 0; c < NC; c++) s += Wd1[lt * NC + c] * ad1[c];
            g_wdst1[lt] = s;
        } else {
            int k = lt - NC;
            float s = 0.f;
            #pragma unroll 4
            for (int c = 0; c < NC; c++) s += Wd2[k * NC + c] * ad2[c];
            g_wdst2[k] = s;
        }
        for (int i = lt; i < NG * NC; i += 256) g_pool[i] = 0.f;
        if (lt < NG) g_cnt[lt] = 0.f;
    }
    if (t < n) g_deg[t] = 0;
}

// --- CSR construction (edge list is launch-invariant: build once, use twice) ---
__global__ void hist_kernel(int E) {
    int e = blockIdx.x * blockDim.x + threadIdx.x;
    if (e < E) atomicAdd(&g_deg[g_dst[e]], 1);
}

// Single-block two-level exclusive scan of deg[0..n)
__global__ void scan_kernel(int n) {
    __shared__ int sSum[1024];
    int t = threadIdx.x;
    int per = (n + 1023) / 1024;
    int lo = t * per;
    int hi = lo + per; if (hi > n) hi = n;
    int s = 0;
    for (int i = lo; i < hi; i++) s += g_deg[i];
    sSum[t] = s;
    __syncthreads();
    for (int off = 1; off < 1024; off <<= 1) {
        int v = (t >= off) ? sSum[t - off] : 0;
        __syncthreads();
        sSum[t] += v;
        __syncthreads();
    }
    int base = (t == 0) ? 0 : sSum[t - 1];
    for (int i = lo; i < hi; i++) {
        g_rowstart[i] = base;
        g_cursor[i]   = base;
        base += g_deg[i];
    }
}

__global__ void fill_kernel(int E) {
    int e = blockIdx.x * blockDim.x + threadIdx.x;
    if (e < E) {
        int slot = atomicAdd(&g_cursor[g_dst[e]], 1);
        g_csr[slot] = e;
    }
}

// K1: fused node GEMM. 256 threads/block, 32 rows/block, warp handles 4 rows.
// layer==0: X = X_ext (raw input).  layer==1: X = relu(g_agg + bias_in).
// Computes g_h = X @ W, g_asrc = h@att, g_adst = X@wdst_layer; zeroes g_denom.
__global__ void node_gemm(const float* __restrict__ X_ext, const float* __restrict__ bias_in,
                          const float* __restrict__ W, const float* __restrict__ att,
                          int layer, int n) {
    __shared__ __align__(16) float sX[32 * NC];
    __shared__ __align__(16) float sAtt[NC];
    __shared__ __align__(16) float sW[NC];
    int t = threadIdx.x;
    int row0 = blockIdx.x * 32;
    const float* wdst = (layer == 0) ? g_wdst1 : g_wdst2;
    const float* X    = (layer == 0) ? X_ext : g_agg;
    if (t < NC) sAtt[t] = att[t];
    else        sW[t - NC] = wdst[t - NC];

    for (int i = t; i < 32 * NC; i += 256) {
        int r = i >> 7, c = i & (NC - 1);
        int gr = row0 + r;
        float v = 0.f;
        if (gr < n) {
            v = X[(size_t)gr * NC + c];
            if (layer == 1) v = fmaxf(v + bias_in[c], 0.f);
        }
        sX[i] = v;
    }
    __syncthreads();

    int warp = t >> 5, lane = t & 31;
    const float* xr = &sX[warp * 4 * NC];
    float4 acc[4];
    #pragma unroll
    for (int r = 0; r < 4; r++) acc[r] = make_float4(0.f, 0.f, 0.f, 0.f);

    const float4* W4 = (const float4*)W;
    #pragma unroll 4
    for (int k = 0; k < NC; k++) {
        float4 w = __ldg(&W4[k * 32 + lane]);
        float x0 = xr[k], x1 = xr[NC + k], x2 = xr[2 * NC + k], x3 = xr[3 * NC + k];
        acc[0].x += x0 * w.x; acc[0].y += x0 * w.y; acc[0].z += x0 * w.z; acc[0].w += x0 * w.w;
        acc[1].x += x1 * w.x; acc[1].y += x1 * w.y; acc[1].z += x1 * w.z; acc[1].w += x1 * w.w;
        acc[2].x += x2 * w.x; acc[2].y += x2 * w.y; acc[2].z += x2 * w.z; acc[2].w += x2 * w.w;
        acc[3].x += x3 * w.x; acc[3].y += x3 * w.y; acc[3].z += x3 * w.z; acc[3].w += x3 * w.w;
    }

    float4 attv = *(const float4*)&sAtt[lane * 4];
    float4 wv   = *(const float4*)&sW[lane * 4];
    #pragma unroll
    for (int r = 0; r < 4; r++) {
        int gr = row0 + warp * 4 + r;
        if (gr < n) {
            float4 a = acc[r];
            *(float4*)&g_h[(size_t)gr * NC + lane * 4] = a;
            float pa = a.x * attv.x + a.y * attv.y + a.z * attv.z + a.w * attv.w;
            const float* xrow = xr + r * NC;
            float pd = xrow[lane * 4 + 0] * wv.x + xrow[lane * 4 + 1] * wv.y +
                       xrow[lane * 4 + 2] * wv.z + xrow[lane * 4 + 3] * wv.w;
            #pragma unroll
            for (int o = 16; o > 0; o >>= 1) {
                pa += __shfl_xor_sync(0xffffffffu, pa, o);
                pd += __shfl_xor_sync(0xffffffffu, pd, o);
            }
            if (lane == 0) { g_asrc[gr] = pa; g_adst[gr] = pd; g_denom[gr] = 0.f; }
        }
    }
}

// K2: per-edge unnormalized softmax weight + denominator accumulation.
// No max subtraction: alpha = exp(e)/sum(exp(e)) is invariant to the shift.
__global__ void edge_softmax(int E) {
    int e = blockIdx.x * blockDim.x + threadIdx.x;
    if (e >= E) return;
    int s = g_src[e], d = g_dst[e];
    float v = g_asrc[s] + g_adst[d];
    v = (v >= 0.f) ? v : 0.2f * v;   // leaky_relu, slope 0.2
    float pe = expf(v);
    g_p[e] = pe;
    atomicAdd(&g_denom[d], pe);
}

// K3: warp-per-dst-node CSR aggregation: g_agg[d] = sum alpha_e * g_h[src_e].
// No atomics on features — register accumulate, single float4 store.
__global__ void aggregate_csr(int n) {
    int node = (blockIdx.x * blockDim.x + threadIdx.x) >> 5;
    int lane = threadIdx.x & 31;
    if (node >= n) return;
    int start = g_rowstart[node];
    int cnt   = g_deg[node];
    float inv = 1.f / (g_denom[node] + 1e-16f);
    float4 acc = make_float4(0.f, 0.f, 0.f, 0.f);
    for (int j0 = 0; j0 < cnt; j0 += 32) {
        int j = j0 + lane;
        int eid = (j < cnt) ? g_csr[start + j] : 0;
        int sN  = (j < cnt) ? g_src[eid] : 0;
        float w = (j < cnt) ? g_p[eid] * inv : 0.f;
        int m = cnt - j0; if (m > 32) m = 32;
        for (int k = 0; k < m; k++) {
            int   sk = __shfl_sync(0xffffffffu, sN, k);
            float wk = __shfl_sync(0xffffffffu, w, k);
            float4 h = *(const float4*)&g_h[(size_t)sk * NC + lane * 4];
            acc.x += wk * h.x; acc.y += wk * h.y; acc.z += wk * h.z; acc.w += wk * h.w;
        }
    }
    *(float4*)&g_agg[(size_t)node * NC + lane * 4] = acc;
}

// K4: mean-pool accumulation: g_pool[batch[n]] += relu(g_agg[n] + bias2)
__global__ void pool_kernel(const float* __restrict__ bias, int n) {
    int nidx = (blockIdx.x * blockDim.x + threadIdx.x) >> 5;
    int lane = threadIdx.x & 31;
    if (nidx >= n) return;
    int g = g_batch[nidx];
    float4 v = *(const float4*)&g_agg[(size_t)nidx * NC + lane * 4];
    float b0 = bias[lane * 4 + 0], b1 = bias[lane * 4 + 1];
    float b2 = bias[lane * 4 + 2], b3 = bias[lane * 4 + 3];
    float* dstp = &g_pool[g * NC + lane * 4];
    atomicAdd(dstp + 0, fmaxf(v.x + b0, 0.f));
    atomicAdd(dstp + 1, fmaxf(v.y + b1, 0.f));
    atomicAdd(dstp + 2, fmaxf(v.z + b2, 0.f));
    atomicAdd(dstp + 3, fmaxf(v.w + b3, 0.f));
    if (lane == 0) atomicAdd(&g_cnt[g], 1.0f);
}

// K5: out = (pool/cnt) @ W_lin + b_lin  (64 x 128)
__global__ void final_linear(const float* __restrict__ Wl, const float* __restrict__ bl,
                             float* __restrict__ out) {
    __shared__ __align__(16) float sP[NC];
    int g = blockIdx.x, c = threadIdx.x;
    sP[c] = g_pool[g * NC + c] / fmaxf(g_cnt[g], 1.0f);
    __syncthreads();
    float acc = bl[c];
    #pragma unroll 4
    for (int k = 0; k < NC; k++) acc += sP[k] * Wl[k * NC + c];
    out[g * NC + c] = acc;
}

extern "C" void kernel_launch(void* const* d_in, const int* in_sizes, int n_in,
                              void* d_out, int out_size) {
    const float* x     = (const float*)d_in[0];
    const void*  ei    = d_in[1];
    const void*  batch = d_in[2];
    const float* Wsrc1   = (const float*)d_in[3];
    const float* Wdst1   = (const float*)d_in[4];
    const float* attsrc1 = (const float*)d_in[5];
    const float* attdst1 = (const float*)d_in[6];
    const float* bias1   = (const float*)d_in[7];
    const float* Wsrc2   = (const float*)d_in[8];
    const float* Wdst2   = (const float*)d_in[9];
    const float* attsrc2 = (const float*)d_in[10];
    const float* attdst2 = (const float*)d_in[11];
    const float* bias2   = (const float*)d_in[12];
    const float* Wlin    = (const float*)d_in[13];
    const float* blin    = (const float*)d_in[14];

    int n = in_sizes[0] / NC;
    int E = in_sizes[1] / 2;

    int gemm_blocks = (n + 31) / 32;
    int e_blocks    = (E + 255) / 256;
    int warp_blocks = (n + 7) / 8;      // warp per node, 8 warps/block
    int prep_blocks = (n + 255) / 256;
    int conv_blocks = ((E > n ? E : n) + 255) / 256;

    detect_kernel<<<1, 256>>>((const int*)ei, E);
    convert_kernel<<<conv_blocks, 256>>>(ei, batch, E, n);
    prep_kernel<<<prep_blocks, 256>>>(Wdst1, attdst1, Wdst2, attdst2, n);

    // CSR build (edge list is identical for both layers)
    hist_kernel<<<e_blocks, 256>>>(E);
    scan_kernel<<<1, 1024>>>(n);
    fill_kernel<<<e_blocks, 256>>>(E);

    // Layer 1
    node_gemm<<<gemm_blocks, 256>>>(x, nullptr, Wsrc1, attsrc1, 0, n);
    edge_softmax<<<e_blocks, 256>>>(E);
    aggregate_csr<<<warp_blocks, 256>>>(n);

    // Layer 2 (input transform relu(g_agg + bias1) applied inside node_gemm)
    node_gemm<<<gemm_blocks, 256>>>(nullptr, bias1, Wsrc2, attsrc2, 1, n);
    edge_softmax<<<e_blocks, 256>>>(E);
    aggregate_csr<<<warp_blocks, 256>>>(n);

    // Pool + head
    pool_kernel<<<warp_blocks, 256>>>(bias2, n);
    final_linear<<<NG, NC>>>(Wlin, blin, (float*)d_out);
}

// round 5
// speedup vs baseline: 1.0248x; 1.0248x over previous
#include <cuda_runtime.h>
#include <math.h>

#define NC 128          // hidden / input dim
#define N_MAX 50000
#define E_MAX 800000
#define NG 64

// ---- scratch (static device globals; no allocation allowed) ----
__device__ float g_h[(size_t)N_MAX * NC];
__device__ float g_agg[(size_t)N_MAX * NC];
__device__ float g_asrc[N_MAX];
__device__ float g_adst[N_MAX];
__device__ float g_pool[NG * NC];
__device__ float g_cnt[NG];
__device__ float g_wdst1[NC];
__device__ float g_wdst2[NC];
// normalized int32 graph structure
__device__ int g_src[E_MAX];
__device__ int g_dst[E_MAX];
__device__ int g_batch[N_MAX];
__device__ int g_is64;
// CSR scratch (g_csr holds SRC node ids grouped by dst)
__device__ int g_deg[N_MAX];
__device__ int g_rowstart[N_MAX];
__device__ int g_cursor[N_MAX];
__device__ int g_csr[E_MAX];

// K0: zero deg/pool, fold W_dst @ att_dst into per-layer 128-vectors.
__global__ void prep_kernel(const float* __restrict__ Wd1, const float* __restrict__ ad1,
                            const float* __restrict__ Wd2, const float* __restrict__ ad2,
                            int n) {
    int t = blockIdx.x * blockDim.x + threadIdx.x;
    if (blockIdx.x == 0) {
        int lt = threadIdx.x;  // 256 threads in block 0
        if (lt < NC) {
            float s = 0.f;
            #pragma unroll 4
            for (int c = 0; c < NC; c++) s += Wd1[lt * NC + c] * ad1[c];
            g_wdst1[lt] = s;
        } else {
            int k = lt - NC;
            float s = 0.f;
            #pragma unroll 4
            for (int c = 0; c < NC; c++) s += Wd2[k * NC + c] * ad2[c];
            g_wdst2[k] = s;
        }
        for (int i = lt; i < NG * NC; i += 256) g_pool[i] = 0.f;
        if (lt < NG) g_cnt[lt] = 0.f;
    }
    if (t < n) g_deg[t] = 0;
}

// K1: detect int64 vs int32 edge_index (JAX x64-off silently emits int32).
__global__ void detect_kernel(const int* __restrict__ ei_words, int E) {
    __shared__ int s_or;
    if (threadIdx.x == 0) s_or = 0;
    __syncthreads();
    int cnt = (E < 2048) ? E : 2048;
    int acc = 0;
    for (int i = threadIdx.x; i < cnt; i += 256) acc |= ei_words[2 * i + 1];
    atomicOr(&s_or, acc);
    __syncthreads();
    if (threadIdx.x == 0) g_is64 = (s_or == 0) ? 1 : 0;
}

// K2: normalize edge_index + batch to int32 AND histogram dst degrees.
__global__ void convert_hist_kernel(const void* __restrict__ ei, const void* __restrict__ batch,
                                    int E, int n) {
    int i = blockIdx.x * blockDim.x + threadIdx.x;
    int is64 = g_is64;
    if (i < E) {
        int s, d;
        if (is64) {
            s = (int)((const long long*)ei)[i];
            d = (int)((const long long*)ei)[E + i];
        } else {
            s = ((const int*)ei)[i];
            d = ((const int*)ei)[E + i];
        }
        g_src[i] = s;
        g_dst[i] = d;
        atomicAdd(&g_deg[d], 1);
    }
    if (i < n) {
        g_batch[i] = is64 ? (int)((const long long*)batch)[i] : ((const int*)batch)[i];
    }
}

// K3: single-block two-level exclusive scan of deg[0..n)
__global__ void scan_kernel(int n) {
    __shared__ int sSum[1024];
    int t = threadIdx.x;
    int per = (n + 1023) / 1024;
    int lo = t * per;
    int hi = lo + per; if (hi > n) hi = n;
    int s = 0;
    for (int i = lo; i < hi; i++) s += g_deg[i];
    sSum[t] = s;
    __syncthreads();
    for (int off = 1; off < 1024; off <<= 1) {
        int v = (t >= off) ? sSum[t - off] : 0;
        __syncthreads();
        sSum[t] += v;
        __syncthreads();
    }
    int base = (t == 0) ? 0 : sSum[t - 1];
    for (int i = lo; i < hi; i++) {
        g_rowstart[i] = base;
        g_cursor[i]   = base;
        base += g_deg[i];
    }
}

// K4: scatter SRC node ids into CSR grouped by dst.
__global__ void fill_kernel(int E) {
    int e = blockIdx.x * blockDim.x + threadIdx.x;
    if (e < E) {
        int slot = atomicAdd(&g_cursor[g_dst[e]], 1);
        g_csr[slot] = g_src[e];
    }
}

// K5: fused node GEMM. 256 threads/block, 32 rows/block, warp handles 4 rows.
// layer==0: X = X_ext.  layer==1: X = relu(g_agg + bias_in).
// Writes g_h = X@W, g_asrc = h@att, g_adst = X@wdst_layer.
__global__ void node_gemm(const float* __restrict__ X_ext, const float* __restrict__ bias_in,
                          const float* __restrict__ W, const float* __restrict__ att,
                          int layer, int n) {
    __shared__ __align__(16) float sX[32 * NC];
    __shared__ __align__(16) float sAtt[NC];
    __shared__ __align__(16) float sW[NC];
    int t = threadIdx.x;
    int row0 = blockIdx.x * 32;
    const float* wdst = (layer == 0) ? g_wdst1 : g_wdst2;
    const float* X    = (layer == 0) ? X_ext : g_agg;
    if (t < NC) sAtt[t] = att[t];
    else        sW[t - NC] = wdst[t - NC];

    for (int i = t; i < 32 * NC; i += 256) {
        int r = i >> 7, c = i & (NC - 1);
        int gr = row0 + r;
        float v = 0.f;
        if (gr < n) {
            v = X[(size_t)gr * NC + c];
            if (layer == 1) v = fmaxf(v + bias_in[c], 0.f);
        }
        sX[i] = v;
    }
    __syncthreads();

    int warp = t >> 5, lane = t & 31;
    const float4* xr4 = (const float4*)&sX[warp * 4 * NC];   // 4 rows, NC/4 float4s each
    float4 acc[4];
    #pragma unroll
    for (int r = 0; r < 4; r++) acc[r] = make_float4(0.f, 0.f, 0.f, 0.f);

    const float4* W4 = (const float4*)W;
    #pragma unroll 2
    for (int k4 = 0; k4 < NC / 4; k4++) {
        float4 x0 = xr4[k4];
        float4 x1 = xr4[32 + k4];
        float4 x2 = xr4[64 + k4];
        float4 x3 = xr4[96 + k4];
        #pragma unroll
        for (int kk = 0; kk < 4; kk++) {
            float4 w = __ldg(&W4[(k4 * 4 + kk) * 32 + lane]);
            float e0 = (&x0.x)[kk], e1 = (&x1.x)[kk], e2 = (&x2.x)[kk], e3 = (&x3.x)[kk];
            acc[0].x += e0 * w.x; acc[0].y += e0 * w.y; acc[0].z += e0 * w.z; acc[0].w += e0 * w.w;
            acc[1].x += e1 * w.x; acc[1].y += e1 * w.y; acc[1].z += e1 * w.z; acc[1].w += e1 * w.w;
            acc[2].x += e2 * w.x; acc[2].y += e2 * w.y; acc[2].z += e2 * w.z; acc[2].w += e2 * w.w;
            acc[3].x += e3 * w.x; acc[3].y += e3 * w.y; acc[3].z += e3 * w.z; acc[3].w += e3 * w.w;
        }
    }

    float4 attv = *(const float4*)&sAtt[lane * 4];
    float4 wv   = *(const float4*)&sW[lane * 4];
    const float* xr = &sX[warp * 4 * NC];
    #pragma unroll
    for (int r = 0; r < 4; r++) {
        int gr = row0 + warp * 4 + r;
        if (gr < n) {
            float4 a = acc[r];
            *(float4*)&g_h[(size_t)gr * NC + lane * 4] = a;
            float pa = a.x * attv.x + a.y * attv.y + a.z * attv.z + a.w * attv.w;
            const float* xrow = xr + r * NC;
            float pd = xrow[lane * 4 + 0] * wv.x + xrow[lane * 4 + 1] * wv.y +
                       xrow[lane * 4 + 2] * wv.z + xrow[lane * 4 + 3] * wv.w;
            #pragma unroll
            for (int o = 16; o > 0; o >>= 1) {
                pa += __shfl_xor_sync(0xffffffffu, pa, o);
                pd += __shfl_xor_sync(0xffffffffu, pd, o);
            }
            if (lane == 0) { g_asrc[gr] = pa; g_adst[gr] = pd; }
        }
    }
}

// K6: fused softmax + CSR aggregation, warp per dst node.
// pass 1: denom = sum exp(leakyrelu(asrc[s]+adst[d]))  (warp reduce, no atomics)
// pass 2: acc   = sum (exp/denom) * g_h[s]             (register accumulate)
// layer==0: write g_agg[node].  layer==1: relu(acc+bias2) -> pool atomics.
__global__ void aggregate_fused(const float* __restrict__ bias2, int layer, int n) {
    int node = (blockIdx.x * blockDim.x + threadIdx.x) >> 5;
    int lane = threadIdx.x & 31;
    if (node >= n) return;
    int start = g_rowstart[node];
    int cnt   = g_deg[node];
    float adst = g_adst[node];

    float dsum = 0.f;
    for (int j = lane; j < cnt; j += 32) {
        int s = g_csr[start + j];
        float v = g_asrc[s] + adst;
        v = (v >= 0.f) ? v : 0.2f * v;
        dsum += __expf(v);
    }
    #pragma unroll
    for (int o = 16; o > 0; o >>= 1) dsum += __shfl_xor_sync(0xffffffffu, dsum, o);
    float inv = 1.f / (dsum + 1e-16f);

    float4 acc = make_float4(0.f, 0.f, 0.f, 0.f);
    for (int j0 = 0; j0 < cnt; j0 += 32) {
        int j = j0 + lane;
        int sN = 0; float w = 0.f;
        if (j < cnt) {
            sN = g_csr[start + j];
            float v = g_asrc[sN] + adst;
            v = (v >= 0.f) ? v : 0.2f * v;
            w = __expf(v) * inv;
        }
        int m = cnt - j0; if (m > 32) m = 32;
        for (int k = 0; k < m; k++) {
            int   sk = __shfl_sync(0xffffffffu, sN, k);
            float wk = __shfl_sync(0xffffffffu, w, k);
            float4 h = *(const float4*)&g_h[(size_t)sk * NC + lane * 4];
            acc.x += wk * h.x; acc.y += wk * h.y; acc.z += wk * h.z; acc.w += wk * h.w;
        }
    }

    if (layer == 0) {
        *(float4*)&g_agg[(size_t)node * NC + lane * 4] = acc;
    } else {
        int g = g_batch[node];
        float b0 = bias2[lane * 4 + 0], b1 = bias2[lane * 4 + 1];
        float b2 = bias2[lane * 4 + 2], b3 = bias2[lane * 4 + 3];
        float* dstp = &g_pool[g * NC + lane * 4];
        atomicAdd(dstp + 0, fmaxf(acc.x + b0, 0.f));
        atomicAdd(dstp + 1, fmaxf(acc.y + b1, 0.f));
        atomicAdd(dstp + 2, fmaxf(acc.z + b2, 0.f));
        atomicAdd(dstp + 3, fmaxf(acc.w + b3, 0.f));
        if (lane == 0) atomicAdd(&g_cnt[g], 1.0f);
    }
}

// K7: out = (pool/cnt) @ W_lin + b_lin  (64 x 128)
__global__ void final_linear(const float* __restrict__ Wl, const float* __restrict__ bl,
                             float* __restrict__ out) {
    __shared__ __align__(16) float sP[NC];
    int g = blockIdx.x, c = threadIdx.x;
    sP[c] = g_pool[g * NC + c] / fmaxf(g_cnt[g], 1.0f);
    __syncthreads();
    float acc = bl[c];
    #pragma unroll 4
    for (int k = 0; k < NC; k++) acc += sP[k] * Wl[k * NC + c];
    out[g * NC + c] = acc;
}

extern "C" void kernel_launch(void* const* d_in, const int* in_sizes, int n_in,
                              void* d_out, int out_size) {
    const float* x     = (const float*)d_in[0];
    const void*  ei    = d_in[1];
    const void*  batch = d_in[2];
    const float* Wsrc1   = (const float*)d_in[3];
    const float* Wdst1   = (const float*)d_in[4];
    const float* attsrc1 = (const float*)d_in[5];
    const float* attdst1 = (const float*)d_in[6];
    const float* bias1   = (const float*)d_in[7];
    const float* Wsrc2   = (const float*)d_in[8];
    const float* Wdst2   = (const float*)d_in[9];
    const float* attsrc2 = (const float*)d_in[10];
    const float* attdst2 = (const float*)d_in[11];
    const float* bias2   = (const float*)d_in[12];
    const float* Wlin    = (const float*)d_in[13];
    const float* blin    = (const float*)d_in[14];

    int n = in_sizes[0] / NC;
    int E = in_sizes[1] / 2;

    int gemm_blocks = (n + 31) / 32;
    int e_blocks    = (E + 255) / 256;
    int warp_blocks = (n + 7) / 8;      // warp per node, 8 warps/block
    int prep_blocks = (n + 255) / 256;
    int conv_blocks = ((E > n ? E : n) + 255) / 256;

    prep_kernel<<<prep_blocks, 256>>>(Wdst1, attdst1, Wdst2, attdst2, n);
    detect_kernel<<<1, 256>>>((const int*)ei, E);
    convert_hist_kernel<<<conv_blocks, 256>>>(ei, batch, E, n);
    scan_kernel<<<1, 1024>>>(n);
    fill_kernel<<<e_blocks, 256>>>(E);

    // Layer 1
    node_gemm<<<gemm_blocks, 256>>>(x, nullptr, Wsrc1, attsrc1, 0, n);
    aggregate_fused<<<warp_blocks, 256>>>(nullptr, 0, n);

    // Layer 2 (input transform relu(g_agg + bias1) inside node_gemm; pool fused)
    node_gemm<<<gemm_blocks, 256>>>(nullptr, bias1, Wsrc2, attsrc2, 1, n);
    aggregate_fused<<<warp_blocks, 256>>>(bias2, 1, n);

    // Head
    final_linear<<<NG, NC>>>(Wlin, blin, (float*)d_out);
}

// round 6
// speedup vs baseline: 1.1668x; 1.1386x over previous
#include <cuda_runtime.h>
#include <math.h>

#define NC 128          // hidden / input dim
#define N_MAX 50000
#define E_MAX 800000
#define NG 64
#define SCAN_EPT 16                       // elems per thread in scan
#define SCAN_CHUNK (256 * SCAN_EPT)       // 4096 elems per block

// ---- scratch (static device globals; no allocation allowed) ----
__device__ float g_h[(size_t)N_MAX * NC];
__device__ float g_agg[(size_t)N_MAX * NC];
__device__ float g_asrc[N_MAX];
__device__ float g_adst[N_MAX];
__device__ float g_pool[NG * NC];
__device__ float g_cnt[NG];
__device__ float g_wdst1[NC];
__device__ float g_wdst2[NC];
// normalized int32 graph structure
__device__ int g_src[E_MAX];
__device__ int g_dst[E_MAX];
__device__ int g_batch[N_MAX];
__device__ int g_is64;
// CSR scratch (g_csr holds SRC node ids grouped by dst)
__device__ int g_deg[N_MAX];
__device__ int g_rowstart[N_MAX];
__device__ int g_cursor[N_MAX];
__device__ int g_csr[E_MAX];
__device__ int g_tsum[(N_MAX + SCAN_CHUNK - 1) / SCAN_CHUNK * 256 + 256];

// K0: zero deg/pool, fold W_dst @ att_dst into per-layer 128-vectors.
__global__ void prep_kernel(const float* __restrict__ Wd1, const float* __restrict__ ad1,
                            const float* __restrict__ Wd2, const float* __restrict__ ad2,
                            int n) {
    int t = blockIdx.x * blockDim.x + threadIdx.x;
    if (blockIdx.x == 0) {
        int lt = threadIdx.x;  // 256 threads in block 0
        if (lt < NC) {
            float s = 0.f;
            #pragma unroll 4
            for (int c = 0; c < NC; c++) s += Wd1[lt * NC + c] * ad1[c];
            g_wdst1[lt] = s;
        } else {
            int k = lt - NC;
            float s = 0.f;
            #pragma unroll 4
            for (int c = 0; c < NC; c++) s += Wd2[k * NC + c] * ad2[c];
            g_wdst2[k] = s;
        }
        for (int i = lt; i < NG * NC; i += 256) g_pool[i] = 0.f;
        if (lt < NG) g_cnt[lt] = 0.f;
    }
    if (t < n) g_deg[t] = 0;
}

// K1: detect int64 vs int32 edge_index (JAX x64-off silently emits int32).
__global__ void detect_kernel(const int* __restrict__ ei_words, int E) {
    __shared__ int s_or;
    if (threadIdx.x == 0) s_or = 0;
    __syncthreads();
    int cnt = (E < 2048) ? E : 2048;
    int acc = 0;
    for (int i = threadIdx.x; i < cnt; i += 256) acc |= ei_words[2 * i + 1];
    atomicOr(&s_or, acc);
    __syncthreads();
    if (threadIdx.x == 0) g_is64 = (s_or == 0) ? 1 : 0;
}

// K2: normalize edge_index + batch to int32 AND histogram dst degrees.
__global__ void convert_hist_kernel(const void* __restrict__ ei, const void* __restrict__ batch,
                                    int E, int n) {
    int i = blockIdx.x * blockDim.x + threadIdx.x;
    int is64 = g_is64;
    if (i < E) {
        int s, d;
        if (is64) {
            s = (int)((const long long*)ei)[i];
            d = (int)((const long long*)ei)[E + i];
        } else {
            s = ((const int*)ei)[i];
            d = ((const int*)ei)[E + i];
        }
        g_src[i] = s;
        g_dst[i] = d;
        atomicAdd(&g_deg[d], 1);
    }
    if (i < n) {
        g_batch[i] = is64 ? (int)((const long long*)batch)[i] : ((const int*)batch)[i];
    }
}

// K3a: per-thread partial sums of 16 degrees each (multi-block, full chip).
__global__ void scan_phase1(int n) {
    int tid = blockIdx.x * blockDim.x + threadIdx.x;
    int base = tid * SCAN_EPT;
    int s = 0;
    #pragma unroll
    for (int i = 0; i < SCAN_EPT; i++) {
        int idx = base + i;
        if (idx < n) s += g_deg[idx];
    }
    g_tsum[tid] = s;
}

// K3b: single-block exclusive scan of the thread-partials (all in SMEM).
__global__ void scan_phase2(int total) {
    __shared__ int sS[1024];
    int t = threadIdx.x;
    int per = (total + 1023) / 1024;
    int lo = t * per;
    int hi = lo + per; if (hi > total) hi = total;
    int s = 0;
    for (int i = lo; i < hi; i++) s += g_tsum[i];
    sS[t] = s;
    __syncthreads();
    for (int off = 1; off < 1024; off <<= 1) {
        int v = (t >= off) ? sS[t - off] : 0;
        __syncthreads();
        sS[t] += v;
        __syncthreads();
    }
    int base = (t == 0) ? 0 : sS[t - 1];
    for (int i = lo; i < hi; i++) {
        int v = g_tsum[i];
        g_tsum[i] = base;
        base += v;
    }
}

// K3c: each thread writes rowstart/cursor for its 16 nodes from its offset.
__global__ void scan_phase3(int n) {
    int tid = blockIdx.x * blockDim.x + threadIdx.x;
    int base = g_tsum[tid];
    int start = tid * SCAN_EPT;
    #pragma unroll
    for (int i = 0; i < SCAN_EPT; i++) {
        int idx = start + i;
        if (idx < n) {
            g_rowstart[idx] = base;
            g_cursor[idx]   = base;
            base += g_deg[idx];
        }
    }
}

// K4: scatter SRC node ids into CSR grouped by dst.
__global__ void fill_kernel(int E) {
    int e = blockIdx.x * blockDim.x + threadIdx.x;
    if (e < E) {
        int slot = atomicAdd(&g_cursor[g_dst[e]], 1);
        g_csr[slot] = g_src[e];
    }
}

// K5: fused node GEMM. 256 threads/block, 32 rows/block, warp handles 4 rows.
// layer==0: X = X_ext.  layer==1: X = relu(g_agg + bias_in).
// Writes g_h = X@W, g_asrc = h@att, g_adst = X@wdst_layer.
__global__ void node_gemm(const float* __restrict__ X_ext, const float* __restrict__ bias_in,
                          const float* __restrict__ W, const float* __restrict__ att,
                          int layer, int n) {
    __shared__ __align__(16) float sX[32 * NC];
    __shared__ __align__(16) float sAtt[NC];
    __shared__ __align__(16) float sW[NC];
    int t = threadIdx.x;
    int row0 = blockIdx.x * 32;
    const float* wdst = (layer == 0) ? g_wdst1 : g_wdst2;
    const float* X    = (layer == 0) ? X_ext : g_agg;
    if (t < NC) sAtt[t] = att[t];
    else        sW[t - NC] = wdst[t - NC];

    for (int i = t; i < 32 * NC; i += 256) {
        int r = i >> 7, c = i & (NC - 1);
        int gr = row0 + r;
        float v = 0.f;
        if (gr < n) {
            v = X[(size_t)gr * NC + c];
            if (layer == 1) v = fmaxf(v + bias_in[c], 0.f);
        }
        sX[i] = v;
    }
    __syncthreads();

    int warp = t >> 5, lane = t & 31;
    const float4* xr4 = (const float4*)&sX[warp * 4 * NC];
    float4 acc[4];
    #pragma unroll
    for (int r = 0; r < 4; r++) acc[r] = make_float4(0.f, 0.f, 0.f, 0.f);

    const float4* W4 = (const float4*)W;
    #pragma unroll 2
    for (int k4 = 0; k4 < NC / 4; k4++) {
        float4 x0 = xr4[k4];
        float4 x1 = xr4[32 + k4];
        float4 x2 = xr4[64 + k4];
        float4 x3 = xr4[96 + k4];
        #pragma unroll
        for (int kk = 0; kk < 4; kk++) {
            float4 w = __ldg(&W4[(k4 * 4 + kk) * 32 + lane]);
            float e0 = (&x0.x)[kk], e1 = (&x1.x)[kk], e2 = (&x2.x)[kk], e3 = (&x3.x)[kk];
            acc[0].x += e0 * w.x; acc[0].y += e0 * w.y; acc[0].z += e0 * w.z; acc[0].w += e0 * w.w;
            acc[1].x += e1 * w.x; acc[1].y += e1 * w.y; acc[1].z += e1 * w.z; acc[1].w += e1 * w.w;
            acc[2].x += e2 * w.x; acc[2].y += e2 * w.y; acc[2].z += e2 * w.z; acc[2].w += e2 * w.w;
            acc[3].x += e3 * w.x; acc[3].y += e3 * w.y; acc[3].z += e3 * w.z; acc[3].w += e3 * w.w;
        }
    }

    float4 attv = *(const float4*)&sAtt[lane * 4];
    float4 wv   = *(const float4*)&sW[lane * 4];
    const float* xr = &sX[warp * 4 * NC];
    #pragma unroll
    for (int r = 0; r < 4; r++) {
        int gr = row0 + warp * 4 + r;
        if (gr < n) {
            float4 a = acc[r];
            *(float4*)&g_h[(size_t)gr * NC + lane * 4] = a;
            float pa = a.x * attv.x + a.y * attv.y + a.z * attv.z + a.w * attv.w;
            const float* xrow = xr + r * NC;
            float pd = xrow[lane * 4 + 0] * wv.x + xrow[lane * 4 + 1] * wv.y +
                       xrow[lane * 4 + 2] * wv.z + xrow[lane * 4 + 3] * wv.w;
            #pragma unroll
            for (int o = 16; o > 0; o >>= 1) {
                pa += __shfl_xor_sync(0xffffffffu, pa, o);
                pd += __shfl_xor_sync(0xffffffffu, pd, o);
            }
            if (lane == 0) { g_asrc[gr] = pa; g_adst[gr] = pd; }
        }
    }
}

// K6: fused softmax + CSR aggregation, warp per dst node.
__global__ void aggregate_fused(const float* __restrict__ bias2, int layer, int n) {
    int node = (blockIdx.x * blockDim.x + threadIdx.x) >> 5;
    int lane = threadIdx.x & 31;
    if (node >= n) return;
    int start = g_rowstart[node];
    int cnt   = g_deg[node];
    float adst = g_adst[node];

    float dsum = 0.f;
    for (int j = lane; j < cnt; j += 32) {
        int s = g_csr[start + j];
        float v = g_asrc[s] + adst;
        v = (v >= 0.f) ? v : 0.2f * v;
        dsum += __expf(v);
    }
    #pragma unroll
    for (int o = 16; o > 0; o >>= 1) dsum += __shfl_xor_sync(0xffffffffu, dsum, o);
    float inv = 1.f / (dsum + 1e-16f);

    float4 acc = make_float4(0.f, 0.f, 0.f, 0.f);
    for (int j0 = 0; j0 < cnt; j0 += 32) {
        int j = j0 + lane;
        int sN = 0; float w = 0.f;
        if (j < cnt) {
            sN = g_csr[start + j];
            float v = g_asrc[sN] + adst;
            v = (v >= 0.f) ? v : 0.2f * v;
            w = __expf(v) * inv;
        }
        int m = cnt - j0; if (m > 32) m = 32;
        for (int k = 0; k < m; k++) {
            int   sk = __shfl_sync(0xffffffffu, sN, k);
            float wk = __shfl_sync(0xffffffffu, w, k);
            float4 h = *(const float4*)&g_h[(size_t)sk * NC + lane * 4];
            acc.x += wk * h.x; acc.y += wk * h.y; acc.z += wk * h.z; acc.w += wk * h.w;
        }
    }

    if (layer == 0) {
        *(float4*)&g_agg[(size_t)node * NC + lane * 4] = acc;
    } else {
        int g = g_batch[node];
        float b0 = bias2[lane * 4 + 0], b1 = bias2[lane * 4 + 1];
        float b2 = bias2[lane * 4 + 2], b3 = bias2[lane * 4 + 3];
        float* dstp = &g_pool[g * NC + lane * 4];
        atomicAdd(dstp + 0, fmaxf(acc.x + b0, 0.f));
        atomicAdd(dstp + 1, fmaxf(acc.y + b1, 0.f));
        atomicAdd(dstp + 2, fmaxf(acc.z + b2, 0.f));
        atomicAdd(dstp + 3, fmaxf(acc.w + b3, 0.f));
        if (lane == 0) atomicAdd(&g_cnt[g], 1.0f);
    }
}

// K7: out = (pool/cnt) @ W_lin + b_lin  (64 x 128)
__global__ void final_linear(const float* __restrict__ Wl, const float* __restrict__ bl,
                             float* __restrict__ out) {
    __shared__ __align__(16) float sP[NC];
    int g = blockIdx.x, c = threadIdx.x;
    sP[c] = g_pool[g * NC + c] / fmaxf(g_cnt[g], 1.0f);
    __syncthreads();
    float acc = bl[c];
    #pragma unroll 4
    for (int k = 0; k < NC; k++) acc += sP[k] * Wl[k * NC + c];
    out[g * NC + c] = acc;
}

extern "C" void kernel_launch(void* const* d_in, const int* in_sizes, int n_in,
                              void* d_out, int out_size) {
    const float* x     = (const float*)d_in[0];
    const void*  ei    = d_in[1];
    const void*  batch = d_in[2];
    const float* Wsrc1   = (const float*)d_in[3];
    const float* Wdst1   = (const float*)d_in[4];
    const float* attsrc1 = (const float*)d_in[5];
    const float* attdst1 = (const float*)d_in[6];
    const float* bias1   = (const float*)d_in[7];
    const float* Wsrc2   = (const float*)d_in[8];
    const float* Wdst2   = (const float*)d_in[9];
    const float* attsrc2 = (const float*)d_in[10];
    const float* attdst2 = (const float*)d_in[11];
    const float* bias2   = (const float*)d_in[12];
    const float* Wlin    = (const float*)d_in[13];
    const float* blin    = (const float*)d_in[14];

    int n = in_sizes[0] / NC;
    int E = in_sizes[1] / 2;

    int gemm_blocks = (n + 31) / 32;
    int e_blocks    = (E + 255) / 256;
    int warp_blocks = (n + 7) / 8;
    int prep_blocks = (n + 255) / 256;
    int conv_blocks = ((E > n ? E : n) + 255) / 256;
    int scan_blocks = (n + SCAN_CHUNK - 1) / SCAN_CHUNK;
    int scan_total  = scan_blocks * 256;

    prep_kernel<<<prep_blocks, 256>>>(Wdst1, attdst1, Wdst2, attdst2, n);
    detect_kernel<<<1, 256>>>((const int*)ei, E);
    convert_hist_kernel<<<conv_blocks, 256>>>(ei, batch, E, n);
    scan_phase1<<<scan_blocks, 256>>>(n);
    scan_phase2<<<1, 1024>>>(scan_total);
    scan_phase3<<<scan_blocks, 256>>>(n);
    fill_kernel<<<e_blocks, 256>>>(E);

    // Layer 1
    node_gemm<<<gemm_blocks, 256>>>(x, nullptr, Wsrc1, attsrc1, 0, n);
    aggregate_fused<<<warp_blocks, 256>>>(nullptr, 0, n);

    // Layer 2
    node_gemm<<<gemm_blocks, 256>>>(nullptr, bias1, Wsrc2, attsrc2, 1, n);
    aggregate_fused<<<warp_blocks, 256>>>(bias2, 1, n);

    // Head
    final_linear<<<NG, NC>>>(Wlin, blin, (float*)d_out);
}